// round 2
// baseline (speedup 1.0000x reference)
#include <cuda_runtime.h>
#include <math.h>
#include <stddef.h>

#define BB   16
#define SSQ  512
#define DDIM 512
#define VV   32000
#define KBM  4
#define TT   64
#define SOS_T 1
#define EOS_T 2
#define PAD_T 0
#define NEGV (-1e9f)

// ---------------- device scratch (static, no runtime alloc) ----------------
__device__ float g_encK[BB * SSQ * DDIM];          // 16 MB
__device__ float g_q[BB * KBM * DDIM];
__device__ float g_att[BB * KBM * SSQ];
__device__ float g_eCtx[BB * KBM * DDIM];
__device__ float g_logits[BB * KBM * VV];          // 8.2 MB
__device__ float g_cand_lp[BB * KBM * KBM];
__device__ int   g_cand_v[BB * KBM * KBM];
__device__ float g_scores[2][BB * KBM];
__device__ int   g_fin[2][BB * KBM];
__device__ int   g_seqs[2][BB * KBM * TT];

// ---------------- tiled fp32 GEMM: C[M,N] = A[M,512] * B[512,N] (+bias) ----
// 64x128 block tile, 256 threads, 4x8 per-thread tile, K-chunk 16.
__device__ __forceinline__ void gemm_body(const float* __restrict__ A,
                                          const float* __restrict__ Bm,
                                          const float* __restrict__ bias,
                                          float* __restrict__ C,
                                          int M, int N)
{
    __shared__ float As[16][64];
    __shared__ float Bs[16][128];
    const int Kd = 512;
    int tid = threadIdx.x;
    int n0 = blockIdx.x * 128;
    int m0 = blockIdx.y * 64;
    int ty = tid >> 4;       // 0..15 -> rows ty*4 .. ty*4+3
    int tx = tid & 15;       // cols: tx*4..+3 and 64+tx*4..+3

    float acc[4][8];
#pragma unroll
    for (int i = 0; i < 4; i++)
#pragma unroll
        for (int j = 0; j < 8; j++) acc[i][j] = 0.f;

    for (int k0 = 0; k0 < Kd; k0 += 16) {
        // stage A tile (64x16) transposed -> As[k][m]
        {
            int m = tid >> 2;
            int ks = (tid & 3) * 4;
            float4 v = make_float4(0.f, 0.f, 0.f, 0.f);
            if (m0 + m < M)
                v = *(const float4*)(A + (size_t)(m0 + m) * Kd + k0 + ks);
            As[ks + 0][m] = v.x; As[ks + 1][m] = v.y;
            As[ks + 2][m] = v.z; As[ks + 3][m] = v.w;
        }
        // stage B tile (16x128)
        {
            int r = tid >> 4;
            int c = (tid & 15) * 8;
            const float* bp = Bm + (size_t)(k0 + r) * N + n0 + c;
            float4 v0 = *(const float4*)bp;
            float4 v1 = *(const float4*)(bp + 4);
            *(float4*)&Bs[r][c] = v0;
            *(float4*)&Bs[r][c + 4] = v1;
        }
        __syncthreads();
#pragma unroll
        for (int kk = 0; kk < 16; kk++) {
            float a0 = As[kk][ty * 4 + 0];
            float a1 = As[kk][ty * 4 + 1];
            float a2 = As[kk][ty * 4 + 2];
            float a3 = As[kk][ty * 4 + 3];
            float4 b0 = *(const float4*)&Bs[kk][tx * 4];
            float4 b1 = *(const float4*)&Bs[kk][64 + tx * 4];
            float bv[8] = {b0.x, b0.y, b0.z, b0.w, b1.x, b1.y, b1.z, b1.w};
#pragma unroll
            for (int j = 0; j < 8; j++) {
                acc[0][j] += a0 * bv[j];
                acc[1][j] += a1 * bv[j];
                acc[2][j] += a2 * bv[j];
                acc[3][j] += a3 * bv[j];
            }
        }
        __syncthreads();
    }

    float4 bias0 = make_float4(0.f, 0.f, 0.f, 0.f);
    float4 bias1 = make_float4(0.f, 0.f, 0.f, 0.f);
    if (bias) {
        bias0 = *(const float4*)(bias + n0 + tx * 4);
        bias1 = *(const float4*)(bias + n0 + 64 + tx * 4);
    }
#pragma unroll
    for (int i = 0; i < 4; i++) {
        int m = m0 + ty * 4 + i;
        if (m < M) {
            float4 o0 = make_float4(acc[i][0] + bias0.x, acc[i][1] + bias0.y,
                                    acc[i][2] + bias0.z, acc[i][3] + bias0.w);
            float4 o1 = make_float4(acc[i][4] + bias1.x, acc[i][5] + bias1.y,
                                    acc[i][6] + bias1.z, acc[i][7] + bias1.w);
            *(float4*)(C + (size_t)m * N + n0 + tx * 4) = o0;
            *(float4*)(C + (size_t)m * N + n0 + 64 + tx * 4) = o1;
        }
    }
}

__global__ __launch_bounds__(256) void k_gemm_encK(const float* __restrict__ enc,
                                                   const float* __restrict__ Wk)
{
    gemm_body(enc, Wk, nullptr, g_encK, BB * SSQ, DDIM);
}

__global__ __launch_bounds__(256) void k_gemm_logits(const float* __restrict__ Wfc,
                                                     const float* __restrict__ bfc)
{
    gemm_body(g_eCtx, Wfc, bfc, g_logits, BB * KBM, VV);
}

// ---------------- embed + q = e @ W_q --------------------------------------
// grid (4 dchunks, 16 b), 512 threads. thread: k = tid>>7, dl = tid&127.
__global__ __launch_bounds__(512) void k_embed_q(const float* __restrict__ emb,
                                                 const float* __restrict__ Wq,
                                                 int init, int t, int par)
{
    __shared__ float se[4][512];
    int b = blockIdx.y, dc = blockIdx.x, tid = threadIdx.x;
    int k = tid >> 7, dl = tid & 127;
    int tok = init ? SOS_T : g_seqs[par][(b * 4 + k) * TT + (t - 1)];
    float4 ev = ((const float4*)(emb + (size_t)tok * DDIM))[dl];
    *(float4*)&se[k][dl * 4] = ev;
    __syncthreads();
    int d = dc * 128 + dl;
    const float* wp = Wq + d;
    float a0 = 0.f, a1 = 0.f, a2 = 0.f, a3 = 0.f;
#pragma unroll 8
    for (int j = 0; j < 512; j += 4) {
        a0 += se[k][j]     * wp[(size_t)j * DDIM];
        a1 += se[k][j + 1] * wp[(size_t)(j + 1) * DDIM];
        a2 += se[k][j + 2] * wp[(size_t)(j + 2) * DDIM];
        a3 += se[k][j + 3] * wp[(size_t)(j + 3) * DDIM];
    }
    g_q[(b * 4 + k) * DDIM + d] = (a0 + a1) + (a2 + a3);
}

// ---------------- attention scores: att = (q . encK) * scale, masked -------
// grid (4 schunks, 16 b), 512 threads = 16 warps, warp-per-dot.
__global__ __launch_bounds__(512) void k_attn(const int* __restrict__ lens, float scale)
{
    __shared__ float sq[4][512];
    int b = blockIdx.y, sc = blockIdx.x, tid = threadIdx.x;
    ((float4*)sq)[tid] = ((const float4*)(g_q + (size_t)b * 4 * DDIM))[tid];
    __syncthreads();
    int warp = tid >> 5, lane = tid & 31;
    int len = lens[b];
    for (int dot = warp; dot < 512; dot += 16) {
        int k = dot >> 7, sl = dot & 127, s = sc * 128 + sl;
        const float4* ek = (const float4*)(g_encK + ((size_t)b * SSQ + s) * DDIM);
        const float4* qk = (const float4*)sq[k];
        float acc = 0.f;
#pragma unroll
        for (int i = 0; i < 4; i++) {
            int j = lane + i * 32;
            float4 a = ek[j], c = qk[j];
            acc += a.x * c.x + a.y * c.y + a.z * c.z + a.w * c.w;
        }
#pragma unroll
        for (int off = 16; off; off >>= 1) acc += __shfl_down_sync(0xffffffffu, acc, off);
        if (lane == 0)
            g_att[(b * 4 + k) * SSQ + s] = (s < len) ? acc * scale : NEGV;
    }
}

// ---------------- softmax + ctx + (e + ctx) --------------------------------
// grid (4 dchunks, 16 b), 512 threads.
__global__ __launch_bounds__(512) void k_ctx(const float* __restrict__ enc,
                                             const float* __restrict__ emb,
                                             int init, int t, int par)
{
    __shared__ float sp[4][512];
    int b = blockIdx.y, dc = blockIdx.x, tid = threadIdx.x;
    ((float4*)sp)[tid] = ((const float4*)(g_att + (size_t)b * 4 * SSQ))[tid];
    __syncthreads();
    int warp = tid >> 5, lane = tid & 31;
    if (warp < 4) {
        int k = warp;
        float m = -3.4e38f;
#pragma unroll
        for (int i = 0; i < 16; i++) m = fmaxf(m, sp[k][lane + i * 32]);
#pragma unroll
        for (int off = 16; off; off >>= 1) m = fmaxf(m, __shfl_xor_sync(0xffffffffu, m, off));
        float sum = 0.f;
        float ev[16];
#pragma unroll
        for (int i = 0; i < 16; i++) {
            float e = expf(sp[k][lane + i * 32] - m);
            ev[i] = e;
            sum += e;
        }
#pragma unroll
        for (int off = 16; off; off >>= 1) sum += __shfl_xor_sync(0xffffffffu, sum, off);
        float inv = 1.f / sum;
#pragma unroll
        for (int i = 0; i < 16; i++) sp[k][lane + i * 32] = ev[i] * inv;
    }
    __syncthreads();
    int k = tid >> 7, dl = tid & 127, d = dc * 128 + dl;
    const float* ep = enc + (size_t)b * SSQ * DDIM + d;
    float a0 = 0.f, a1 = 0.f, a2 = 0.f, a3 = 0.f;
#pragma unroll 4
    for (int s = 0; s < 512; s += 4) {
        a0 += sp[k][s]     * ep[(size_t)s * DDIM];
        a1 += sp[k][s + 1] * ep[(size_t)(s + 1) * DDIM];
        a2 += sp[k][s + 2] * ep[(size_t)(s + 2) * DDIM];
        a3 += sp[k][s + 3] * ep[(size_t)(s + 3) * DDIM];
    }
    int tok = init ? SOS_T : g_seqs[par][(b * 4 + k) * TT + (t - 1)];
    g_eCtx[(b * 4 + k) * DDIM + d] = emb[(size_t)tok * DDIM + d] + ((a0 + a1) + (a2 + a3));
}

// ---------------- per-row logsumexp + top-4 (jax tie semantics) ------------
// grid 64 rows, 256 threads.
__global__ __launch_bounds__(256) void k_rowreduce()
{
    int r = blockIdx.x;
    const float* L = g_logits + (size_t)r * VV;
    int tid = threadIdx.x;
    __shared__ float sred[256];

    float m = -3.4e38f;
    for (int j = tid; j < VV; j += 256) m = fmaxf(m, L[j]);
    sred[tid] = m;
    __syncthreads();
    for (int off = 128; off; off >>= 1) {
        if (tid < off) sred[tid] = fmaxf(sred[tid], sred[tid + off]);
        __syncthreads();
    }
    float M = sred[0];
    __syncthreads();

    float sum = 0.f;
    float tv[4] = {-3.4e38f, -3.4e38f, -3.4e38f, -3.4e38f};
    int   ti[4] = {0x7fffffff, 0x7fffffff, 0x7fffffff, 0x7fffffff};
    for (int j = tid; j < VV; j += 256) {
        float v = L[j];
        sum += expf(v - M);
        if (v > tv[3]) {
            if (v > tv[0]) {
                tv[3] = tv[2]; ti[3] = ti[2]; tv[2] = tv[1]; ti[2] = ti[1];
                tv[1] = tv[0]; ti[1] = ti[0]; tv[0] = v; ti[0] = j;
            } else if (v > tv[1]) {
                tv[3] = tv[2]; ti[3] = ti[2]; tv[2] = tv[1]; ti[2] = ti[1];
                tv[1] = v; ti[1] = j;
            } else if (v > tv[2]) {
                tv[3] = tv[2]; ti[3] = ti[2]; tv[2] = v; ti[2] = j;
            } else {
                tv[3] = v; ti[3] = j;
            }
        }
    }
    sred[tid] = sum;
    __syncthreads();
    for (int off = 128; off; off >>= 1) {
        if (tid < off) sred[tid] += sred[tid + off];
        __syncthreads();
    }
    float lse = M + logf(sred[0]);
    __syncthreads();

    __shared__ float cv[1024];
    __shared__ int   ct[1024];
    __shared__ float rv[256];
    __shared__ int   rt[256];
    __shared__ int   rs[256];
#pragma unroll
    for (int i = 0; i < 4; i++) { cv[tid * 4 + i] = tv[i]; ct[tid * 4 + i] = ti[i]; }

    for (int round = 0; round < 4; round++) {
        __syncthreads();
        float bv = -3.4e38f; int bt = 0x7fffffff; int bs = -1;
        for (int j = tid; j < 1024; j += 256) {
            float v = cv[j]; int tk = ct[j];
            if (v > bv || (v == bv && tk < bt)) { bv = v; bt = tk; bs = j; }
        }
        rv[tid] = bv; rt[tid] = bt; rs[tid] = bs;
        __syncthreads();
        for (int off = 128; off; off >>= 1) {
            if (tid < off) {
                float v = rv[tid + off]; int tk = rt[tid + off];
                if (v > rv[tid] || (v == rv[tid] && tk < rt[tid])) {
                    rv[tid] = v; rt[tid] = tk; rs[tid] = rs[tid + off];
                }
            }
            __syncthreads();
        }
        if (tid == 0) {
            g_cand_lp[r * 4 + round] = rv[0] - lse;
            g_cand_v[r * 4 + round] = rt[0];
            cv[rs[0]] = -3.4e38f;
        }
    }
}

// ---------------- first-step beam init -------------------------------------
__global__ void k_init_select()
{
    int b = blockIdx.x, tid = threadIdx.x;   // 64 threads
    __shared__ int stok[4];
    if (tid < 4) {
        float v = g_cand_lp[(b * 4 + 0) * 4 + tid];
        int tok = g_cand_v[(b * 4 + 0) * 4 + tid];
        g_scores[0][b * 4 + tid] = v;
        g_fin[0][b * 4 + tid] = (tok == EOS_T) ? 1 : 0;
        stok[tid] = tok;
    }
    __syncthreads();
    for (int idx = tid; idx < KBM * TT; idx += 64) {
        int k = idx >> 6, p = idx & 63;
        int val = (p == 0) ? SOS_T : ((p == 1) ? stok[k] : PAD_T);
        g_seqs[0][(b * 4 + k) * TT + p] = val;
    }
}

// ---------------- per-step beam combine ------------------------------------
__global__ void k_combine(int t, int par)
{
    int b = blockIdx.x, tid = threadIdx.x;   // 64 threads
    __shared__ float nsc[4];
    __shared__ int nbi[4], ntok[4], nfin[4];
    if (tid == 0) {
        float tot[16]; int tvv[16];
        for (int j = 0; j < 4; j++) {
            int f = g_fin[par][b * 4 + j];
            float sc = g_scores[par][b * 4 + j];
            for (int rr = 0; rr < 4; rr++) {
                float lp; int v;
                if (f) { lp = (rr == 0) ? 0.f : NEGV; v = PAD_T; }
                else   { lp = g_cand_lp[(b * 4 + j) * 4 + rr]; v = g_cand_v[(b * 4 + j) * 4 + rr]; }
                tot[j * 4 + rr] = sc + lp;
                tvv[j * 4 + rr] = v;
            }
        }
        bool used[16];
        for (int i = 0; i < 16; i++) used[i] = false;
        for (int k = 0; k < 4; k++) {
            int best = -1;
            for (int i = 0; i < 16; i++)
                if (!used[i] && (best < 0 || tot[i] > tot[best])) best = i;
            used[best] = true;
            nsc[k] = tot[best]; nbi[k] = best >> 2; ntok[k] = tvv[best];
        }
        for (int k = 0; k < 4; k++)
            nfin[k] = (g_fin[par][b * 4 + nbi[k]] || ntok[k] == EOS_T) ? 1 : 0;
    }
    __syncthreads();
    int np = par ^ 1;
    for (int idx = tid; idx < 4 * TT; idx += 64) {
        int k = idx >> 6, p = idx & 63;
        int src = g_seqs[par][(b * 4 + nbi[k]) * TT + p];
        g_seqs[np][(b * 4 + k) * TT + p] = (p == t) ? ntok[k] : src;
    }
    if (tid < 4) {
        g_scores[np][b * 4 + tid] = nsc[tid];
        g_fin[np][b * 4 + tid] = nfin[tid];
    }
}

// ---------------- final selection + output ---------------------------------
__global__ void k_final(float* __restrict__ out, int out_size, int par)
{
    __shared__ int bk[16];
    __shared__ float bvv[16];
    int tid = threadIdx.x;   // 1024 threads
    if (tid < 16) {
        float bs = -3.4e38f; int bi = 0;
        for (int k = 0; k < 4; k++) {
            float v = g_scores[par][tid * 4 + k];
            if (v > bs) { bs = v; bi = k; }
        }
        bk[tid] = bi; bvv[tid] = bs;
    }
    __syncthreads();
    if (tid < BB * TT && tid < out_size) {
        int b = tid >> 6, p = tid & 63;
        out[tid] = (float)g_seqs[par][(b * 4 + bk[b]) * TT + p];
    }
    if (tid < 16 && BB * TT + tid < out_size)
        out[BB * TT + tid] = bvv[tid];
}

// ---------------- launch ----------------------------------------------------
extern "C" void kernel_launch(void* const* d_in, const int* in_sizes, int n_in,
                              void* d_out, int out_size)
{
    const float* enc  = (const float*)d_in[0];
    const int*   lens = (const int*)d_in[1];
    const float* emb  = (const float*)d_in[2];
    const float* Wq   = (const float*)d_in[3];
    const float* Wk   = (const float*)d_in[4];
    const float* Wfc  = (const float*)d_in[5];
    const float* bfc  = (const float*)d_in[6];
    float* out = (float*)d_out;
    float scale = 1.0f / sqrtf(512.0f);

    // encK = enc @ W_k  (once per launch; deterministic)
    k_gemm_encK<<<dim3(4, 128), 256>>>(enc, Wk);

    // step 1: expand SOS -> top-K beams
    k_embed_q<<<dim3(4, 16), 512>>>(emb, Wq, 1, 0, 0);
    k_attn<<<dim3(4, 16), 512>>>(lens, scale);
    k_ctx<<<dim3(4, 16), 512>>>(enc, emb, 1, 0, 0);
    k_gemm_logits<<<dim3(250, 1), 256>>>(Wfc, bfc);
    k_rowreduce<<<64, 256>>>();
    k_init_select<<<16, 64>>>();

    int par = 0;
    for (int t = 2; t < TT; t++) {
        k_embed_q<<<dim3(4, 16), 512>>>(emb, Wq, 0, t, par);
        k_attn<<<dim3(4, 16), 512>>>(lens, scale);
        k_ctx<<<dim3(4, 16), 512>>>(enc, emb, 0, t, par);
        k_gemm_logits<<<dim3(250, 1), 256>>>(Wfc, bfc);
        k_rowreduce<<<64, 256>>>();
        k_combine<<<16, 64>>>(t, par);
        par ^= 1;
    }

    k_final<<<1, 1024>>>(out, out_size, par);
}